// round 5
// baseline (speedup 1.0000x reference)
#include <cuda_runtime.h>
#include <cstdint>

#define H  16
#define S  4096
#define DH 128
#define DM 2048
#define BM 128
#define BN 128
#define NT 512            // 16 warps

#define SROW 136          // floats per packed SMEM row (conflict-free LDS.64)

// float offsets within dynamic SMEM
#define F_Q   0
#define F_KP  (F_Q + BM*SROW)       // K tile (packed), later P tile (packed)
#define F_V   (F_KP + BM*SROW)
#define F_X1  (F_V + BN*SROW)      // rowmax exchange
#define F_X2  (F_X1 + 512)          // rowsum exchange
#define SMEM_FLOATS (F_X2 + 512)
#define SMEM_BYTES  (SMEM_FLOATS * 4)   // 212,992 B

// Prepass scratch: tf32-rounded, pair-packed tensors
// Qp/Kp: [head][row][128] with each 8-col block permuted (x0,x4,x1,x5,x2,x6,x3,x7)
// Vp:    [head][kvTile(32)][d(128)][128] pairs over kv, same permute
__device__ float g_Qs[H * S * DH];
__device__ float g_Ks[H * S * DH];
__device__ float g_Vs[H * S * DH];

__device__ __forceinline__ float tfr(float f){
    uint32_t r; asm("cvt.rna.tf32.f32 %0, %1;" : "=r"(r) : "f"(f));
    return __uint_as_float(r);
}
__device__ __forceinline__ float ex2f(float x){
    float r; asm("ex2.approx.ftz.f32 %0, %1;" : "=f"(r) : "f"(x)); return r;
}
__device__ __forceinline__ void mma_tf32(float c[4],
    float a0, float a1, float a2, float a3, float b0, float b1)
{
    asm volatile(
        "mma.sync.aligned.m16n8k8.row.col.f32.tf32.tf32.f32 "
        "{%0,%1,%2,%3}, {%4,%5,%6,%7}, {%8,%9}, {%0,%1,%2,%3};\n"
        : "+f"(c[0]), "+f"(c[1]), "+f"(c[2]), "+f"(c[3])
        : "r"(__float_as_uint(a0)), "r"(__float_as_uint(a1)),
          "r"(__float_as_uint(a2)), "r"(__float_as_uint(a3)),
          "r"(__float_as_uint(b0)), "r"(__float_as_uint(b1)));
}
__device__ __forceinline__ void cpa16(uint32_t dst, const float* src){
    asm volatile("cp.async.cg.shared.global [%0], [%1], 16;" :: "r"(dst), "l"(src));
}
__device__ __forceinline__ void cpa_commit(){
    asm volatile("cp.async.commit_group;" ::: "memory");
}
__device__ __forceinline__ void cpa_wait0(){
    asm volatile("cp.async.wait_group 0;" ::: "memory");
}

// ---- Prepass 1: Q,K -> tf32, pair-packed rows (Q pre-scaled) ----
__global__ void prep_qk(const float* __restrict__ Q, const float* __restrict__ K)
{
    const float SC = 0.088388347648318447f * 1.4426950408889634f; // 1/sqrt(128)*log2e
    size_t t = (size_t)blockIdx.x * blockDim.x + threadIdx.x;   // H*S*16 threads
    size_t base = t * 8;                                         // 8 cols per thread
    float4 qa = *(const float4*)(Q + base);
    float4 qb = *(const float4*)(Q + base + 4);
    float4 ka = *(const float4*)(K + base);
    float4 kb = *(const float4*)(K + base + 4);
    // out order: (x0,x4,x1,x5) (x2,x6,x3,x7)
    *(float4*)(g_Qs + base)     = make_float4(tfr(qa.x*SC), tfr(qb.x*SC), tfr(qa.y*SC), tfr(qb.y*SC));
    *(float4*)(g_Qs + base + 4) = make_float4(tfr(qa.z*SC), tfr(qb.z*SC), tfr(qa.w*SC), tfr(qb.w*SC));
    *(float4*)(g_Ks + base)     = make_float4(tfr(ka.x), tfr(kb.x), tfr(ka.y), tfr(kb.y));
    *(float4*)(g_Ks + base + 4) = make_float4(tfr(ka.z), tfr(kb.z), tfr(ka.w), tfr(kb.w));
}

// ---- Prepass 2: V -> tf32, transposed per 128-kv tile, pair-packed over kv ----
__global__ void prep_v(const float* __restrict__ V)
{
    int b    = blockIdx.x;          // 16*32*16 blocks
    int kb   = b & 15;
    int T    = (b >> 4) & 31;
    int head = b >> 9;
    int d    = threadIdx.x;         // 128
    int kv0  = T * 128 + kb * 8;
    const float* src = V + ((size_t)head * S + kv0) * DH + d;
    float x[8];
    #pragma unroll
    for (int w = 0; w < 8; ++w) x[w] = tfr(src[(size_t)w * DH]);
    float* dst = g_Vs + (((size_t)head * 32 + T) * 128 + d) * 128 + kb * 8;
    *(float4*)(dst)     = make_float4(x[0], x[4], x[1], x[5]);
    *(float4*)(dst + 4) = make_float4(x[2], x[6], x[3], x[7]);
}

// ---------------- Main flash-attention kernel ----------------
extern __shared__ float sm[];

__global__ __launch_bounds__(NT, 1)
void fa_kernel(float* __restrict__ Out)
{
    const int qt   = (int)gridDim.x - 1 - (int)blockIdx.x;  // heavy tiles first
    const int head = blockIdx.y;
    const int q0   = qt * BM;
    const int tid  = threadIdx.x;
    const int lane = tid & 31;
    const int warp = tid >> 5;
    const int gid  = lane >> 2;
    const int t4   = lane & 3;
    const int rg   = warp >> 2;           // row group: rows mbase..mbase+31
    const int ch   = warp & 3;            // col quarter
    const int mbase = rg * 32;
    const int nbase = ch * 32;
    const int dbase = ch * 32;

    const uint32_t smb = (uint32_t)__cvta_generic_to_shared(sm);
    const float NEGINF = __int_as_float(0xff800000);

    const float* gQ  = g_Qs + ((size_t)head * S + q0) * DH;
    const float* gKh = g_Ks + (size_t)head * S * DH;
    const float* gVh = g_Vs + (size_t)head * S * DH;   // [tile][d][128] packed

    // packed P store offsets for this thread (within its 8-col block)
    const int w2 = 2 * t4;
    const int e0 = 2 * (w2 & 3) + (w2 >> 2);           // col c   (even)
    const int e1 = 2 * ((w2 + 1) & 3) + ((w2 + 1) >> 2); // col c+1 (odd)

    // ---- Prologue: async load Q tile + KV tile 0 ----
    #pragma unroll
    for (int it = 0; it < 8; ++it){
        int i = it * NT + tid;
        int row = i >> 5, f4 = (i & 31) << 2;
        cpa16(smb + (uint32_t)(F_Q + row * SROW + f4) * 4, gQ + row * DH + f4);
    }
    #pragma unroll
    for (int it = 0; it < 8; ++it){
        int i = it * NT + tid;
        int row = i >> 5, f4 = (i & 31) << 2;
        cpa16(smb + (uint32_t)(F_KP + row * SROW + f4) * 4, gKh + row * DH + f4);
        cpa16(smb + (uint32_t)(F_V  + row * SROW + f4) * 4, gVh + row * DH + f4);
    }
    cpa_commit();

    float o[2][4][4];
    #pragma unroll
    for (int a = 0; a < 2; ++a)
        #pragma unroll
        for (int b = 0; b < 4; ++b)
            o[a][b][0] = o[a][b][1] = o[a][b][2] = o[a][b][3] = 0.f;
    float m[4] = {NEGINF, NEGINF, NEGINF, NEGINF};
    float l[4] = {0.f, 0.f, 0.f, 0.f};

    #pragma unroll 1
    for (int j = 0; j <= qt; ++j){
        cpa_wait0();
        __syncthreads();

        // ---- MMA1: S = Q * K^T  (32 rows x 32 cols per warp) ----
        float sa[2][4][4];
        #pragma unroll
        for (int a = 0; a < 2; ++a)
            #pragma unroll
            for (int b = 0; b < 4; ++b)
                sa[a][b][0] = sa[a][b][1] = sa[a][b][2] = sa[a][b][3] = 0.f;

        #pragma unroll
        for (int ks = 0; ks < 16; ++ks){
            int co = ks * 8 + w2;
            const float* qr = sm + F_Q + (mbase + gid) * SROW + co;
            float2 A02 = *(const float2*)(qr);              // a0,a2 rows gid
            float2 A13 = *(const float2*)(qr + 8*SROW);     // a1,a3 rows gid+8
            float2 A46 = *(const float2*)(qr + 16*SROW);
            float2 A57 = *(const float2*)(qr + 24*SROW);
            #pragma unroll
            for (int nt = 0; nt < 4; ++nt){
                float2 B = *(const float2*)(sm + F_KP + (nbase + nt*8 + gid) * SROW + co);
                mma_tf32(sa[0][nt], A02.x, A13.x, A02.y, A13.y, B.x, B.y);
                mma_tf32(sa[1][nt], A46.x, A57.x, A46.y, A57.y, B.x, B.y);
            }
        }

        // ---- Causal mask on diagonal tile ----
        if (j == qt){
            #pragma unroll
            for (int mg = 0; mg < 2; ++mg){
                int r0 = mbase + 16*mg + gid, r1 = r0 + 8;
                #pragma unroll
                for (int nt = 0; nt < 4; ++nt){
                    int c = nbase + nt*8 + w2;
                    if (c     > r0) sa[mg][nt][0] = NEGINF;
                    if (c + 1 > r0) sa[mg][nt][1] = NEGINF;
                    if (c     > r1) sa[mg][nt][2] = NEGINF;
                    if (c + 1 > r1) sa[mg][nt][3] = NEGINF;
                }
            }
        }

        // ---- Partial row max, exchange across the 4 column-warps ----
        float mx[4] = {NEGINF, NEGINF, NEGINF, NEGINF};
        #pragma unroll
        for (int nt = 0; nt < 4; ++nt){
            mx[0] = fmaxf(mx[0], fmaxf(sa[0][nt][0], sa[0][nt][1]));
            mx[1] = fmaxf(mx[1], fmaxf(sa[0][nt][2], sa[0][nt][3]));
            mx[2] = fmaxf(mx[2], fmaxf(sa[1][nt][0], sa[1][nt][1]));
            mx[3] = fmaxf(mx[3], fmaxf(sa[1][nt][2], sa[1][nt][3]));
        }
        #pragma unroll
        for (int i = 0; i < 4; ++i){
            mx[i] = fmaxf(mx[i], __shfl_xor_sync(0xffffffffu, mx[i], 1));
            mx[i] = fmaxf(mx[i], __shfl_xor_sync(0xffffffffu, mx[i], 2));
        }
        if (t4 == 0){
            #pragma unroll
            for (int i = 0; i < 4; ++i)
                sm[F_X1 + (mbase + gid + 8*i)*4 + ch] = mx[i];
        }
        __syncthreads();   // all warps done reading K -> P store into F_KP safe

        float mn[4], al[4];
        #pragma unroll
        for (int i = 0; i < 4; ++i){
            int b = F_X1 + (mbase + gid + 8*i)*4;
            float v = fmaxf(fmaxf(sm[b], sm[b+1]), fmaxf(sm[b+2], sm[b+3]));
            mn[i] = fmaxf(m[i], v);
            al[i] = ex2f(m[i] - mn[i]);
            m[i]  = mn[i];
        }

        // ---- P = exp2(S - m); store packed into K buffer; partial row sums ----
        float rs[4] = {0.f, 0.f, 0.f, 0.f};
        #pragma unroll
        for (int mg = 0; mg < 2; ++mg){
            #pragma unroll
            for (int nt = 0; nt < 4; ++nt){
                float p0 = ex2f(sa[mg][nt][0] - mn[2*mg]);
                float p1 = ex2f(sa[mg][nt][1] - mn[2*mg]);
                float p2 = ex2f(sa[mg][nt][2] - mn[2*mg+1]);
                float p3 = ex2f(sa[mg][nt][3] - mn[2*mg+1]);
                rs[2*mg]   += p0 + p1;
                rs[2*mg+1] += p2 + p3;
                int base8 = nbase + 8*nt;
                float* pr0 = sm + F_KP + (mbase + 16*mg + gid) * SROW + base8;
                float* pr1 = pr0 + 8 * SROW;
                pr0[e0] = p0;  pr0[e1] = p1;
                pr1[e0] = p2;  pr1[e1] = p3;
            }
        }
        #pragma unroll
        for (int i = 0; i < 4; ++i){
            rs[i] += __shfl_xor_sync(0xffffffffu, rs[i], 1);
            rs[i] += __shfl_xor_sync(0xffffffffu, rs[i], 2);
        }
        if (t4 == 0){
            #pragma unroll
            for (int i = 0; i < 4; ++i)
                sm[F_X2 + (mbase + gid + 8*i)*4 + ch] = rs[i];
        }
        asm volatile("bar.sync %0, 128;" :: "r"(1 + rg) : "memory");  // row-group barrier

        #pragma unroll
        for (int i = 0; i < 4; ++i){
            int b = F_X2 + (mbase + gid + 8*i)*4;
            l[i] = l[i]*al[i] + (sm[b] + sm[b+1] + sm[b+2] + sm[b+3]);
        }
        // rescale O
        #pragma unroll
        for (int mg = 0; mg < 2; ++mg){
            #pragma unroll
            for (int nt = 0; nt < 4; ++nt){
                o[mg][nt][0] *= al[2*mg];   o[mg][nt][1] *= al[2*mg];
                o[mg][nt][2] *= al[2*mg+1]; o[mg][nt][3] *= al[2*mg+1];
            }
        }

        // ---- MMA2: O += P * V  (P packed in K buffer, V packed over kv) ----
        #pragma unroll
        for (int ks = 0; ks < 16; ++ks){
            int co = ks * 8 + w2;
            const float* pr = sm + F_KP + (mbase + gid) * SROW + co;
            float2 A02 = *(const float2*)(pr);
            float2 A13 = *(const float2*)(pr + 8*SROW);
            float2 A46 = *(const float2*)(pr + 16*SROW);
            float2 A57 = *(const float2*)(pr + 24*SROW);
            #pragma unroll
            for (int nt = 0; nt < 4; ++nt){
                float2 B = *(const float2*)(sm + F_V + (dbase + nt*8 + gid) * SROW + co);
                mma_tf32(o[0][nt], A02.x, A13.x, A02.y, A13.y, B.x, B.y);
                mma_tf32(o[1][nt], A46.x, A57.x, A46.y, A57.y, B.x, B.y);
            }
        }

        __syncthreads();   // all reads of P (K buf) and V done
        if (j < qt){
            const float* gK = gKh + (size_t)(j + 1) * BN * DH;
            const float* gV = gVh + (size_t)(j + 1) * BN * DH;   // next tile block
            #pragma unroll
            for (int it = 0; it < 8; ++it){
                int i = it * NT + tid;
                int row = i >> 5, f4 = (i & 31) << 2;
                cpa16(smb + (uint32_t)(F_KP + row * SROW + f4) * 4, gK + row * DH + f4);
                cpa16(smb + (uint32_t)(F_V  + row * SROW + f4) * 4, gV + row * DH + f4);
            }
            cpa_commit();
        }
    }

    // ---- Epilogue: O / l -> Out[(q0+row), head*128 + d] ----
    #pragma unroll
    for (int mg = 0; mg < 2; ++mg){
        int r0 = q0 + mbase + 16*mg + gid;
        float i0 = 1.0f / l[2*mg];
        float i1 = 1.0f / l[2*mg + 1];
        #pragma unroll
        for (int nt = 0; nt < 4; ++nt){
            int c = head * DH + dbase + nt*8 + w2;
            *(float2*)(Out + (size_t)r0 * DM + c) =
                make_float2(o[mg][nt][0] * i0, o[mg][nt][1] * i0);
            *(float2*)(Out + (size_t)(r0 + 8) * DM + c) =
                make_float2(o[mg][nt][2] * i1, o[mg][nt][3] * i1);
        }
    }
}

extern "C" void kernel_launch(void* const* d_in, const int* in_sizes, int n_in,
                              void* d_out, int out_size)
{
    (void)in_sizes; (void)n_in; (void)out_size;
    const float* q = (const float*)d_in[0];
    const float* k = (const float*)d_in[1];
    const float* v = (const float*)d_in[2];
    float* out = (float*)d_out;

    prep_qk<<<(H * S * 16) / 256, 256>>>(q, k);
    prep_v<<<H * 32 * 16, 128>>>(v);

    cudaFuncSetAttribute(fa_kernel,
                         cudaFuncAttributeMaxDynamicSharedMemorySize, SMEM_BYTES);
    dim3 grid(S / BM, H);
    fa_kernel<<<grid, NT, SMEM_BYTES>>>(out);
}